// round 1
// baseline (speedup 1.0000x reference)
#include <cuda_runtime.h>
#include <math.h>

// ---------------- problem constants ----------------
#define B_    2
#define CIN   512
#define S_    1024
#define D_    768
#define H_    12
#define HD_   64
#define E_    8
#define KTOP  2
#define L_    2
#define FF_   2048
#define NFFT_ 1024
#define HOP_  256
#define WIN_  1024
#define PAD_  384
#define FB_   513          // NFFT/2+1
#define NTOK  (B_*S_)      // 2048
#define NSLOT (NTOK*KTOP)  // 4096
#define OUTL  262144       // (S-1)*HOP + WIN - 2*PAD

// ---------------- scratch (static device globals; no allocation) ----------------
__device__ float g_zt[NTOK*CIN];
__device__ float g_x[NTOK*D_];
__device__ float g_h[NTOK*D_];
__device__ float g_q[NTOK*D_];
__device__ float g_k[NTOK*D_];
__device__ float g_v[NTOK*D_];
__device__ float g_ctx[NTOK*D_];
__device__ float g_sc[(long)B_*H_*S_*S_];   // 100 MB attention scores
__device__ float g_h1[(long)NSLOT*FF_];     // MoE hidden
__device__ float g_y[(long)NSLOT*D_];       // MoE expert outputs
__device__ float g_sout[(long)NTOK*(2*FB_)];
__device__ float g_dft[(long)(2*FB_)*NFFT_];
__device__ float g_frames[(long)NTOK*NFFT_];
__device__ int   g_topi[NSLOT];
__device__ float g_topw[NSLOT];
__device__ int   g_rank[NSLOT];
__device__ int   g_cnt[E_];
__device__ int   g_off[E_+1];
__device__ int   g_slot_tok[NSLOT];
__device__ int   g_tok_slot[NSLOT];
__device__ int   g_blkmap[80];
__device__ int   g_nblk[1];

// ---------------- helpers ----------------
__device__ __forceinline__ float gelu_f(float x) {
    float x3 = x*x*x;
    return 0.5f*x*(1.f + tanhf(0.79788456080286535588f*(x + 0.044715f*x3)));
}

// ---------------- generic tiled SGEMM ----------------
// C[m,n] = act(alpha * sum_k A[m,k]*B[k,n] + bias[n]) + res[m,n]
// Two-level batch: z -> (z/bH)*sX + (z%bH)*sX2 offsets.
// MOE mode: blockIdx.y indexes a (expert,row-tile) map built on device;
//           rows are slots [off[e], off[e+1]); A rows optionally gathered.
template<bool TRANSB, bool GELU, bool MOE>
__global__ __launch_bounds__(256) void gemm64(
    const float* __restrict__ A, int lda, long sA, long sA2,
    const float* __restrict__ Bm, int ldb, long sB, long sB2,
    float* __restrict__ C, int ldc, long sC, long sC2,
    const float* __restrict__ bias, long sBiasE,
    const float* __restrict__ res,
    int M, int N, int K, float alpha, int bH,
    const int* __restrict__ gather,
    const int* __restrict__ off, const int* __restrict__ blkmap,
    const int* __restrict__ nblk, long sBexp)
{
    int z = blockIdx.z;
    long aoff = (long)(z / bH)*sA + (long)(z % bH)*sA2;
    long boff = (long)(z / bH)*sB + (long)(z % bH)*sB2;
    long coff = (long)(z / bH)*sC + (long)(z % bH)*sC2;
    const float* Ab = A + aoff;
    const float* Bb = Bm + boff;
    float*       Cb = C + coff;
    const float* resb = res ? res + coff : nullptr;

    int col0 = blockIdx.x*64;
    int row0, Meff, rbase = 0, expert = 0;
    if (MOE) {
        if ((int)blockIdx.y >= *nblk) return;
        int mp = blkmap[blockIdx.y];
        expert = mp >> 16;
        rbase  = off[expert];
        Meff   = off[expert+1] - rbase;
        row0   = (mp & 0xffff)*64;
        Bb     = Bm + (long)expert*sBexp;
    } else {
        row0 = blockIdx.y*64; Meff = M;
    }

    __shared__ float As[16][68];
    __shared__ float Bs[16][68];
    int tid = threadIdx.x;
    int tx = tid & 15, ty = tid >> 4;
    float acc[4][4] = {};

    for (int k0 = 0; k0 < K; k0 += 16) {
        #pragma unroll
        for (int it = 0; it < 4; it++) {
            int li = tid + it*256;
            int m = li >> 4, kk = li & 15;
            float v = 0.f;
            int gm = row0 + m;
            if (gm < Meff && (k0+kk) < K) {
                int ar;
                if (MOE) ar = gather ? gather[rbase+gm] : (rbase+gm);
                else     ar = gm;
                v = Ab[(long)ar*lda + k0 + kk];
            }
            As[kk][m] = v;
        }
        #pragma unroll
        for (int it = 0; it < 4; it++) {
            int li = tid + it*256;
            float v = 0.f;
            if (!TRANSB) {
                int kk = li >> 6, n = li & 63;
                if ((k0+kk) < K && (col0+n) < N) v = Bb[(long)(k0+kk)*ldb + col0 + n];
                Bs[kk][n] = v;
            } else {
                int n = li >> 4, kk = li & 15;
                if ((k0+kk) < K && (col0+n) < N) v = Bb[(long)(col0+n)*ldb + k0 + kk];
                Bs[kk][n] = v;
            }
        }
        __syncthreads();
        #pragma unroll
        for (int kk = 0; kk < 16; kk++) {
            float a[4], b[4];
            #pragma unroll
            for (int i = 0; i < 4; i++) a[i] = As[kk][ty*4+i];
            #pragma unroll
            for (int j = 0; j < 4; j++) b[j] = Bs[kk][tx*4+j];
            #pragma unroll
            for (int i = 0; i < 4; i++)
                #pragma unroll
                for (int j = 0; j < 4; j++)
                    acc[i][j] = fmaf(a[i], b[j], acc[i][j]);
        }
        __syncthreads();
    }

    const float* biasb = bias ? (MOE ? bias + (long)expert*sBiasE : bias) : nullptr;
    #pragma unroll
    for (int i = 0; i < 4; i++) {
        int gm = row0 + ty*4 + i;
        if (gm >= Meff) continue;
        long crow = MOE ? (long)(rbase+gm) : (long)gm;
        #pragma unroll
        for (int j = 0; j < 4; j++) {
            int gn = col0 + tx*4 + j;
            if (gn >= N) continue;
            float v = acc[i][j]*alpha;
            if (biasb) v += biasb[gn];
            if (GELU)  v = gelu_f(v);
            if (resb)  v += resb[crow*ldc + gn];
            Cb[crow*ldc + gn] = v;
        }
    }
}

// ---------------- transpose z [B,C,S] -> zt [B*S, C] ----------------
__global__ void transpose_kernel(const float* __restrict__ z) {
    __shared__ float tile[32][33];
    int b  = blockIdx.z;
    int s0 = blockIdx.x*32, c0 = blockIdx.y*32;
    int tx = threadIdx.x, ty = threadIdx.y;
    // read coalesced along s
    tile[ty][tx] = z[((long)b*CIN + (c0+ty))*S_ + s0 + tx];
    __syncthreads();
    // write coalesced along c
    g_zt[((long)b*S_ + (s0+ty))*CIN + c0 + tx] = tile[tx][ty];
}

// ---------------- layernorm ----------------
__global__ void ln_kernel(const float* __restrict__ x, float* __restrict__ o,
                          const float* __restrict__ g, const float* __restrict__ b) {
    int row = blockIdx.x;
    const float* xr = x + (long)row*D_;
    __shared__ float red[256];
    int tid = threadIdx.x;
    float s = 0.f;
    for (int j = tid; j < D_; j += 256) s += xr[j];
    red[tid] = s; __syncthreads();
    for (int st = 128; st > 0; st >>= 1) { if (tid < st) red[tid] += red[tid+st]; __syncthreads(); }
    float mean = red[0] / D_;
    __syncthreads();
    float v = 0.f;
    for (int j = tid; j < D_; j += 256) { float d = xr[j]-mean; v += d*d; }
    red[tid] = v; __syncthreads();
    for (int st = 128; st > 0; st >>= 1) { if (tid < st) red[tid] += red[tid+st]; __syncthreads(); }
    float rstd = rsqrtf(red[0]/D_ + 1e-5f);
    for (int j = tid; j < D_; j += 256)
        o[(long)row*D_ + j] = (xr[j]-mean)*rstd*g[j] + b[j];
}

// ---------------- RoPE over full hidden dim (interleaved pairs) ----------------
__global__ void rope_kernel(float* q, float* k) {
    int t = blockIdx.x;           // 0..NTOK-1
    int s = t % S_;
    int j = threadIdx.x;          // 0..383
    float inv = expf(-logf(10000.f) * ((float)j / 384.f));
    float ang = (float)s * inv;
    float sn, cs; sincosf(ang, &sn, &cs);
    long base = (long)t*D_ + 2*j;
    float x1 = q[base], x2 = q[base+1];
    q[base]   = x1*cs - x2*sn;
    q[base+1] = x1*sn + x2*cs;
    x1 = k[base]; x2 = k[base+1];
    k[base]   = x1*cs - x2*sn;
    k[base+1] = x1*sn + x2*cs;
}

// ---------------- causal row softmax (writes 0 beyond the diagonal) ----------------
__global__ void softmax_causal(float* __restrict__ sc) {
    long row = blockIdx.x;
    int i = (int)(row % S_);
    float* p = sc + row*(long)S_;
    int tid = threadIdx.x;
    __shared__ float red[256];
    float m = -1e30f;
    for (int j = tid; j <= i; j += 256) m = fmaxf(m, p[j]);
    red[tid] = m; __syncthreads();
    for (int st = 128; st > 0; st >>= 1) { if (tid < st) red[tid] = fmaxf(red[tid], red[tid+st]); __syncthreads(); }
    m = red[0]; __syncthreads();
    float s = 0.f;
    for (int j = tid; j <= i; j += 256) { float e = expf(p[j]-m); p[j] = e; s += e; }
    red[tid] = s; __syncthreads();
    for (int st = 128; st > 0; st >>= 1) { if (tid < st) red[tid] += red[tid+st]; __syncthreads(); }
    float inv = 1.f / red[0];
    for (int j = tid; j <= i; j += 256) p[j] *= inv;
    for (int j = i+1+tid; j < S_; j += 256) p[j] = 0.f;
}

// ---------------- MoE gating ----------------
__global__ void zero_cnt_kernel() { if (threadIdx.x < E_) g_cnt[threadIdx.x] = 0; }

__global__ void gate_kernel(const float* __restrict__ h, const float* __restrict__ gw) {
    int warp = threadIdx.x >> 5, lane = threadIdx.x & 31;
    int t = blockIdx.x*8 + warp;
    if (t >= NTOK) return;
    const float* hr = h + (long)t*D_;
    float lg[E_];
    #pragma unroll
    for (int e = 0; e < E_; e++) lg[e] = 0.f;
    for (int d = lane; d < D_; d += 32) {
        float hv = hr[d];
        #pragma unroll
        for (int e = 0; e < E_; e++) lg[e] += hv * gw[(long)d*E_ + e];
    }
    #pragma unroll
    for (int e = 0; e < E_; e++)
        for (int st = 16; st > 0; st >>= 1) lg[e] += __shfl_xor_sync(0xffffffffu, lg[e], st);
    if (lane == 0) {
        int i0 = 0; float v0 = lg[0];
        for (int e = 1; e < E_; e++) if (lg[e] > v0) { v0 = lg[e]; i0 = e; }
        int i1 = -1; float v1 = -1e30f;
        for (int e = 0; e < E_; e++) if (e != i0 && lg[e] > v1) { v1 = lg[e]; i1 = e; }
        float e0 = 1.f;               // exp(v0-v0)
        float e1 = expf(v1 - v0);
        float inv = 1.f/(e0+e1);
        g_topi[t*2] = i0;   g_topi[t*2+1] = i1;
        g_topw[t*2] = e0*inv; g_topw[t*2+1] = e1*inv;
        g_rank[t*2]   = atomicAdd(&g_cnt[i0], 1);
        g_rank[t*2+1] = atomicAdd(&g_cnt[i1], 1);
    }
}

__global__ void scan_kernel() {
    g_off[0] = 0;
    int nb = 0;
    for (int e = 0; e < E_; e++) {
        g_off[e+1] = g_off[e] + g_cnt[e];
        int tiles = (g_cnt[e] + 63) / 64;
        for (int tI = 0; tI < tiles; tI++) g_blkmap[nb++] = (e << 16) | tI;
    }
    g_nblk[0] = nb;
}

__global__ void fill_slots_kernel() {
    int idx = blockIdx.x*256 + threadIdx.x;
    if (idx >= NSLOT) return;
    int e = g_topi[idx];
    int slot = g_off[e] + g_rank[idx];
    g_slot_tok[slot] = idx >> 1;
    g_tok_slot[idx] = slot;
}

__global__ void combine_kernel(float* __restrict__ x) {
    int t = blockIdx.x;
    int s0 = g_tok_slot[t*2], s1 = g_tok_slot[t*2+1];
    float w0 = g_topw[t*2], w1 = g_topw[t*2+1];
    for (int j = threadIdx.x; j < D_; j += 256)
        x[(long)t*D_+j] += w0*g_y[(long)s0*D_+j] + w1*g_y[(long)s1*D_+j];
}

// ---------------- windowed inverse-DFT matrix (built per call) ----------------
__global__ void dft_build_kernel() {
    int r = blockIdx.y;                       // 0..1025
    int n = blockIdx.x*256 + threadIdx.x;     // 0..1023
    const float TWO_PI = 6.283185307179586477f;
    float win = 0.5f*(1.f - cosf(TWO_PI * (float)n / (float)NFFT_));
    float val;
    if (r < FB_) {
        float w = (r == 0 || r == FB_-1) ? 1.f : 2.f;
        int ph = (r*n) & (NFFT_-1);
        val = (w/(float)NFFT_) * cosf(TWO_PI * (float)ph / (float)NFFT_) * win;
    } else {
        int r2 = r - FB_;
        float w = (r2 == 0 || r2 == FB_-1) ? 1.f : 2.f;
        int ph = (r2*n) & (NFFT_-1);
        val = -(w/(float)NFFT_) * sinf(TWO_PI * (float)ph / (float)NFFT_) * win;
    }
    g_dft[(long)r*NFFT_ + n] = val;
}

// ---------------- overlap-add + env normalize + trim ----------------
__global__ void ola_kernel(float* __restrict__ out) {
    int b = blockIdx.y;
    int p = blockIdx.x*256 + threadIdx.x;     // 0..OUTL-1
    int g = p + PAD_;
    int tmin = (g >= WIN_-1) ? ((g - (WIN_-1) + HOP_-1) >> 8) : 0;
    int tmax = g >> 8;
    if (tmax > S_-1) tmax = S_-1;
    const float TWO_PI = 6.283185307179586477f;
    float acc = 0.f, env = 0.f;
    for (int t = tmin; t <= tmax; t++) {
        int n = g - t*HOP_;
        float win = 0.5f*(1.f - cosf(TWO_PI * (float)n / (float)WIN_));
        acc += g_frames[((long)(b*S_ + t))*NFFT_ + n];
        env += win*win;
    }
    out[(long)b*OUTL + p] = acc/env;
}

// ---------------- host orchestration ----------------
extern "C" void kernel_launch(void* const* d_in, const int* in_sizes, int n_in,
                              void* d_out, int out_size) {
    (void)in_sizes; (void)n_in; (void)out_size;
    const float* z     = (const float*)d_in[0];
    const float* in_w  = (const float*)d_in[1];
    const float* in_b  = (const float*)d_in[2];
    const float* ln1_g = (const float*)d_in[3];
    const float* ln1_b = (const float*)d_in[4];
    const float* wq    = (const float*)d_in[5];
    const float* bq    = (const float*)d_in[6];
    const float* wk    = (const float*)d_in[7];
    const float* bk    = (const float*)d_in[8];
    const float* wv    = (const float*)d_in[9];
    const float* bv    = (const float*)d_in[10];
    const float* wo    = (const float*)d_in[11];
    const float* bo    = (const float*)d_in[12];
    const float* ln2_g = (const float*)d_in[13];
    const float* ln2_b = (const float*)d_in[14];
    const float* gatew = (const float*)d_in[15];
    const float* e_w1  = (const float*)d_in[16];
    const float* e_b1  = (const float*)d_in[17];
    const float* e_w2  = (const float*)d_in[18];
    const float* e_b2  = (const float*)d_in[19];
    const float* out_w = (const float*)d_in[20];
    const float* out_b = (const float*)d_in[21];
    float* out = (float*)d_out;

    float *p_zt,*p_x,*p_h,*p_q,*p_k,*p_v,*p_ctx,*p_sc,*p_h1,*p_y,*p_s,*p_fr,*p_dft;
    int *p_slot_tok,*p_off,*p_blkmap,*p_nblk;
    cudaGetSymbolAddress((void**)&p_zt, g_zt);
    cudaGetSymbolAddress((void**)&p_x,  g_x);
    cudaGetSymbolAddress((void**)&p_h,  g_h);
    cudaGetSymbolAddress((void**)&p_q,  g_q);
    cudaGetSymbolAddress((void**)&p_k,  g_k);
    cudaGetSymbolAddress((void**)&p_v,  g_v);
    cudaGetSymbolAddress((void**)&p_ctx,g_ctx);
    cudaGetSymbolAddress((void**)&p_sc, g_sc);
    cudaGetSymbolAddress((void**)&p_h1, g_h1);
    cudaGetSymbolAddress((void**)&p_y,  g_y);
    cudaGetSymbolAddress((void**)&p_s,  g_sout);
    cudaGetSymbolAddress((void**)&p_fr, g_frames);
    cudaGetSymbolAddress((void**)&p_dft,g_dft);
    cudaGetSymbolAddress((void**)&p_slot_tok, g_slot_tok);
    cudaGetSymbolAddress((void**)&p_off,    g_off);
    cudaGetSymbolAddress((void**)&p_blkmap, g_blkmap);
    cudaGetSymbolAddress((void**)&p_nblk,   g_nblk);

    // in-projection: zt = z^T per batch, then x = zt @ in_w + in_b
    transpose_kernel<<<dim3(S_/32, CIN/32, B_), dim3(32,32)>>>(z);
    gemm64<false,false,false><<<dim3(D_/64, NTOK/64, 1), 256>>>(
        p_zt, CIN, 0,0, in_w, D_, 0,0, p_x, D_, 0,0,
        in_b, 0, nullptr, NTOK, D_, CIN, 1.f, 1,
        nullptr, nullptr, nullptr, nullptr, 0);

    for (int i = 0; i < L_; i++) {
        // ---- attention ----
        ln_kernel<<<NTOK,256>>>(p_x, p_h, ln1_g + i*D_, ln1_b + i*D_);
        gemm64<false,false,false><<<dim3(D_/64, NTOK/64, 1), 256>>>(
            p_h, D_, 0,0, wq + (long)i*D_*D_, D_, 0,0, p_q, D_, 0,0,
            bq + i*D_, 0, nullptr, NTOK, D_, D_, 1.f, 1, nullptr,nullptr,nullptr,nullptr,0);
        gemm64<false,false,false><<<dim3(D_/64, NTOK/64, 1), 256>>>(
            p_h, D_, 0,0, wk + (long)i*D_*D_, D_, 0,0, p_k, D_, 0,0,
            bk + i*D_, 0, nullptr, NTOK, D_, D_, 1.f, 1, nullptr,nullptr,nullptr,nullptr,0);
        gemm64<false,false,false><<<dim3(D_/64, NTOK/64, 1), 256>>>(
            p_h, D_, 0,0, wv + (long)i*D_*D_, D_, 0,0, p_v, D_, 0,0,
            bv + i*D_, 0, nullptr, NTOK, D_, D_, 1.f, 1, nullptr,nullptr,nullptr,nullptr,0);
        if (i == 0) rope_kernel<<<NTOK,384>>>(p_q, p_k);

        // scores = (Q @ K^T) * 1/sqrt(HD), per (b,h)
        gemm64<true,false,false><<<dim3(S_/64, S_/64, B_*H_), 256>>>(
            p_q, D_, (long)S_*D_, 64, p_k, D_, (long)S_*D_, 64,
            p_sc, S_, (long)H_*S_*S_, (long)S_*S_,
            nullptr, 0, nullptr, S_, S_, HD_, 0.125f, H_,
            nullptr,nullptr,nullptr,nullptr,0);
        softmax_causal<<<B_*H_*S_,256>>>(p_sc);
        // ctx = att @ V
        gemm64<false,false,false><<<dim3(1, S_/64, B_*H_), 256>>>(
            p_sc, S_, (long)H_*S_*S_, (long)S_*S_, p_v, D_, (long)S_*D_, 64,
            p_ctx, D_, (long)S_*D_, 64,
            nullptr, 0, nullptr, S_, HD_, S_, 1.f, H_,
            nullptr,nullptr,nullptr,nullptr,0);
        // x += ctx @ Wo + bo
        gemm64<false,false,false><<<dim3(D_/64, NTOK/64, 1), 256>>>(
            p_ctx, D_, 0,0, wo + (long)i*D_*D_, D_, 0,0, p_x, D_, 0,0,
            bo + i*D_, 0, p_x, NTOK, D_, D_, 1.f, 1, nullptr,nullptr,nullptr,nullptr,0);

        // ---- MoE ----
        ln_kernel<<<NTOK,256>>>(p_x, p_h, ln2_g + i*D_, ln2_b + i*D_);
        zero_cnt_kernel<<<1,32>>>();
        gate_kernel<<<NTOK/8,256>>>(p_h, gatew + (long)i*D_*E_);
        scan_kernel<<<1,1>>>();
        fill_slots_kernel<<<(NSLOT+255)/256,256>>>();
        // h1[slot] = gelu(h[token] @ w1[e] + b1[e])
        gemm64<false,true,true><<<dim3(FF_/64, 72, 1), 256>>>(
            p_h, D_, 0,0, e_w1 + (long)i*E_*D_*FF_, FF_, 0,0,
            p_h1, FF_, 0,0, e_b1 + (long)i*E_*FF_, FF_,
            nullptr, 0, FF_, D_, 1.f, 1,
            p_slot_tok, p_off, p_blkmap, p_nblk, (long)D_*FF_);
        // y[slot] = h1[slot] @ w2[e] + b2[e]
        gemm64<false,false,true><<<dim3(D_/64, 72, 1), 256>>>(
            p_h1, FF_, 0,0, e_w2 + (long)i*E_*FF_*D_, D_, 0,0,
            p_y, D_, 0,0, e_b2 + (long)i*E_*D_, D_,
            nullptr, 0, D_, FF_, 1.f, 1,
            nullptr, p_off, p_blkmap, p_nblk, (long)FF_*D_);
        combine_kernel<<<NTOK,256>>>(p_x);
    }

    // spectral head: s = x @ out_w + out_b   [2048, 1026]
    gemm64<false,false,false><<<dim3((2*FB_+63)/64, NTOK/64, 1), 256>>>(
        p_x, D_, 0,0, out_w, 2*FB_, 0,0, p_s, 2*FB_, 0,0,
        out_b, 0, nullptr, NTOK, 2*FB_, D_, 1.f, 1,
        nullptr,nullptr,nullptr,nullptr,0);

    // windowed inverse DFT as a GEMM: frames = s @ M   [2048, 1024]
    dft_build_kernel<<<dim3(NFFT_/256, 2*FB_), 256>>>();
    gemm64<false,false,false><<<dim3(NFFT_/64, NTOK/64, 1), 256>>>(
        p_s, 2*FB_, 0,0, p_dft, NFFT_, 0,0, p_fr, NFFT_, 0,0,
        nullptr, 0, nullptr, NTOK, NFFT_, 2*FB_, 1.f, 1,
        nullptr,nullptr,nullptr,nullptr,0);

    // overlap-add, normalize, trim
    ola_kernel<<<dim3(OUTL/256, B_), 256>>>(out);
}

// round 12
// speedup vs baseline: 1.0096x; 1.0096x over previous
#include <cuda_runtime.h>
#include <cuda_bf16.h>
#include <math.h>
#include <stdint.h>

// ---------------- problem constants ----------------
#define B_    2
#define CIN   512
#define S_    1024
#define D_    768
#define H_    12
#define HD_   64
#define E_    8
#define KTOP  2
#define L_    2
#define FF_   2048
#define NFFT_ 1024
#define HOP_  256
#define WIN_  1024
#define PAD_  384
#define FB_   513
#define NTOK  (B_*S_)      // 2048
#define NSLOT (NTOK*KTOP)  // 4096
#define OUTL  262144
#define SLD   1028         // padded row stride for spectral head output

// ---------------- scratch ----------------
__device__ float g_zt[NTOK*CIN];
__device__ float g_x[NTOK*D_];
__device__ float g_h[NTOK*D_];
__device__ float g_q[NTOK*D_];
__device__ float g_k[NTOK*D_];
__device__ float g_v[NTOK*D_];
__device__ float g_ctx[NTOK*D_];
__device__ float g_sc[(long)B_*H_*S_*S_];
__device__ float g_h1[(long)NSLOT*FF_];
__device__ float g_y[(long)NSLOT*D_];
__device__ float g_sout[(long)NTOK*SLD];
__device__ float g_dft[(long)(2*FB_)*NFFT_];
__device__ float g_frames[(long)NTOK*NFFT_];
__device__ int   g_topi[NSLOT];
__device__ float g_topw[NSLOT];
__device__ int   g_rank[NSLOT];
__device__ int   g_cnt[E_];
__device__ int   g_off[E_+1];
__device__ int   g_slot_tok[NSLOT];
__device__ int   g_tok_slot[NSLOT];
__device__ int   g_blkmap[80];
__device__ int   g_nblk[1];

// ---------------- helpers ----------------
__device__ __forceinline__ float gelu_f(float x) {
    float x3 = x*x*x;
    return 0.5f*x*(1.f + tanhf(0.79788456080286535588f*(x + 0.044715f*x3)));
}
__device__ __forceinline__ uint32_t smem_u32(const void* p) {
    uint32_t a;
    asm("{ .reg .u64 t; cvta.to.shared.u64 t, %1; cvt.u32.u64 %0, t; }" : "=r"(a) : "l"(p));
    return a;
}
__device__ __forceinline__ uint32_t packbf(__nv_bfloat16 a, __nv_bfloat16 b) {
    __nv_bfloat162 t = __halves2bfloat162(a, b);
    return *reinterpret_cast<uint32_t*>(&t);
}
__device__ __forceinline__ uint32_t swz(uint32_t off) { return off ^ ((off >> 3) & 0x70); }

__device__ __forceinline__ void ldsm4(uint32_t& r0, uint32_t& r1, uint32_t& r2, uint32_t& r3, uint32_t addr) {
    asm volatile("ldmatrix.sync.aligned.m8n8.x4.shared.b16 {%0,%1,%2,%3}, [%4];"
                 : "=r"(r0), "=r"(r1), "=r"(r2), "=r"(r3) : "r"(addr));
}
__device__ __forceinline__ void mma16816(float* c, const uint32_t* a, uint32_t b0, uint32_t b1) {
    asm volatile("mma.sync.aligned.m16n8k16.row.col.f32.bf16.bf16.f32 "
                 "{%0,%1,%2,%3}, {%4,%5,%6,%7}, {%8,%9}, {%0,%1,%2,%3};"
                 : "+f"(c[0]), "+f"(c[1]), "+f"(c[2]), "+f"(c[3])
                 : "r"(a[0]), "r"(a[1]), "r"(a[2]), "r"(a[3]), "r"(b0), "r"(b1));
}

// convert a float4 -> hi/lo bf16, 8-byte stores to swizzled smem (4 contiguous K elems)
__device__ __forceinline__ void store8hl(char* smem, int offH, int offL, uint32_t byteoff, float4 v) {
    uint32_t sw = swz(byteoff);
    __nv_bfloat16 hx = __float2bfloat16(v.x);
    __nv_bfloat16 hy = __float2bfloat16(v.y);
    __nv_bfloat16 hz = __float2bfloat16(v.z);
    __nv_bfloat16 hw = __float2bfloat16(v.w);
    uint2 hv; hv.x = packbf(hx, hy); hv.y = packbf(hz, hw);
    *reinterpret_cast<uint2*>(smem + offH + sw) = hv;
    __nv_bfloat16 lx = __float2bfloat16(v.x - __bfloat162float(hx));
    __nv_bfloat16 ly = __float2bfloat16(v.y - __bfloat162float(hy));
    __nv_bfloat16 lz = __float2bfloat16(v.z - __bfloat162float(hz));
    __nv_bfloat16 lw = __float2bfloat16(v.w - __bfloat162float(hw));
    uint2 lv; lv.x = packbf(lx, ly); lv.y = packbf(lz, lw);
    *reinterpret_cast<uint2*>(smem + offL + sw) = lv;
}

// ---------------- tensor-core split-bf16 GEMM (mma.sync path, works on bare sm_103) ----------------
// C[m,n] = act(alpha * sum_k A[m,k]*B[...] + bias[n]) (+ res[m,n])
// CTA tile 128 x BN, K-chunks of 64. 8 warps in 4x2; warp = 32 rows x BN/2 cols.
template<bool TRANSB, bool GELU, bool MOE, int BN, bool CSKIP, bool CKLIM>
__global__ __launch_bounds__(256) void gemmtc(
    const float* __restrict__ A, int lda, long sA, long sA2,
    const float* __restrict__ Bm, int ldb, long sB, long sB2,
    float* __restrict__ C, int ldc, long sC, long sC2,
    const float* __restrict__ bias, long sBiasE,
    const float* __restrict__ res,
    int M, int N, int K, float alpha, int bH,
    const int* __restrict__ gather, const int* __restrict__ off,
    const int* __restrict__ blkmap, const int* __restrict__ nblk, long sBexp)
{
    extern __shared__ char smem[];
    constexpr int SM_AHI = 0;
    constexpr int SM_ALO = SM_AHI + 128*128;
    constexpr int SM_BHI = SM_ALO + 128*128;
    constexpr int SM_BLO = SM_BHI + BN*128;
    constexpr int WN = BN/2;      // warp col extent
    constexpr int NT = BN/16;     // 8x8-col n-blocks per warp

    int z = blockIdx.z;
    long aoff = (long)(z / bH)*sA + (long)(z % bH)*sA2;
    long boff = (long)(z / bH)*sB + (long)(z % bH)*sB2;
    long coff = (long)(z / bH)*sC + (long)(z % bH)*sC2;
    const float* Ab = A + aoff;
    const float* Bb = Bm + boff;
    float*       Cb = C + coff;
    const float* resb = res ? res + coff : nullptr;

    int col0 = blockIdx.x*BN;
    int row0, Meff, rbase = 0, expert = 0;
    if (MOE) {
        if ((int)blockIdx.y >= *nblk) return;
        int mp = blkmap[blockIdx.y];
        expert = mp >> 16;
        rbase  = off[expert];
        Meff   = off[expert+1] - rbase;
        row0   = (mp & 0xffff)*128;
        Bb     = Bm + (long)expert*sBexp;
    } else { row0 = blockIdx.y*128; Meff = M; }

    if (CSKIP && col0 > row0 + 127) return;
    int Klim = CKLIM ? min(K, row0 + 128) : K;
    int nch = (Klim + 63) >> 6;

    uint32_t sb = smem_u32(smem);
    int tid = threadIdx.x, wid = tid >> 5, lane = tid & 31;
    int wm = wid & 3, wn = wid >> 2;

    float acc[2][NT][4];
    #pragma unroll
    for (int mt = 0; mt < 2; mt++)
        #pragma unroll
        for (int nt = 0; nt < NT; nt++)
            #pragma unroll
            for (int q = 0; q < 4; q++) acc[mt][nt][q] = 0.f;

    for (int c = 0; c < nch; c++) {
        int k0 = c << 6;
        __syncthreads();
        // ---- A tile (128 x 64) ----
        #pragma unroll
        for (int it = 0; it < 8; it++) {
            int li = tid + it*256;
            int m = li >> 4, k4 = (li & 15) << 2;
            int gm = row0 + m, gk = k0 + k4;
            float4 v = make_float4(0.f, 0.f, 0.f, 0.f);
            if (!MOE || gm < Meff) {
                long ar;
                if (MOE) ar = gather ? (long)gather[rbase + gm] : (long)(rbase + gm);
                else     ar = gm;
                const float* p = Ab + ar*(long)lda + gk;
                if (gk + 3 < K) v = *(const float4*)p;
                else {
                    if (gk   < K) v.x = p[0];
                    if (gk+1 < K) v.y = p[1];
                    if (gk+2 < K) v.z = p[2];
                    if (gk+3 < K) v.w = p[3];
                }
            }
            store8hl(smem, SM_AHI, SM_ALO, (uint32_t)(m*128 + k4*2), v);
        }
        // ---- B tile (BN x 64), stored n-major / k-contiguous ----
        if (TRANSB) {
            #pragma unroll
            for (int it = 0; it < BN/16; it++) {
                int li = tid + it*256;
                int n = li >> 4, k4 = (li & 15) << 2;
                int gn = col0 + n, gk = k0 + k4;
                float4 v = make_float4(0.f, 0.f, 0.f, 0.f);
                if (gn < N) {
                    const float* p = Bb + (long)gn*ldb + gk;
                    if (gk + 3 < K) v = *(const float4*)p;
                    else {
                        if (gk   < K) v.x = p[0];
                        if (gk+1 < K) v.y = p[1];
                        if (gk+2 < K) v.z = p[2];
                        if (gk+3 < K) v.w = p[3];
                    }
                }
                store8hl(smem, SM_BHI, SM_BLO, (uint32_t)(n*128 + k4*2), v);
            }
        } else {
            #pragma unroll
            for (int it = 0; it < BN/16; it++) {
                int li = tid + it*256;
                int k = li / (BN/4);
                int n4 = (li % (BN/4)) << 2;
                int gk = k0 + k, gn = col0 + n4;
                float4 v = make_float4(0.f, 0.f, 0.f, 0.f);
                if (gk < K) {
                    const float* p = Bb + (long)gk*ldb + gn;
                    if (((ldb & 3) == 0) && gn + 3 < N) v = *(const float4*)p;
                    else {
                        if (gn   < N) v.x = p[0];
                        if (gn+1 < N) v.y = p[1];
                        if (gn+2 < N) v.z = p[2];
                        if (gn+3 < N) v.w = p[3];
                    }
                }
                float vv[4] = {v.x, v.y, v.z, v.w};
                #pragma unroll
                for (int q = 0; q < 4; q++) {
                    uint32_t sw = swz((uint32_t)((n4+q)*128 + k*2));
                    __nv_bfloat16 h = __float2bfloat16(vv[q]);
                    *reinterpret_cast<__nv_bfloat16*>(smem + SM_BHI + sw) = h;
                    *reinterpret_cast<__nv_bfloat16*>(smem + SM_BLO + sw) =
                        __float2bfloat16(vv[q] - __bfloat162float(h));
                }
            }
        }
        __syncthreads();
        // ---- compute: 4 k-steps of 16 ----
        #pragma unroll
        for (int ks = 0; ks < 4; ks++) {
            uint32_t ah[2][4], al[2][4];
            #pragma unroll
            for (int mt = 0; mt < 2; mt++) {
                int r = wm*32 + mt*16 + (lane & 15);
                uint32_t sa = swz((uint32_t)(r*128 + ks*32 + ((lane >> 4)&1)*16));
                ldsm4(ah[mt][0], ah[mt][1], ah[mt][2], ah[mt][3], sb + SM_AHI + sa);
                ldsm4(al[mt][0], al[mt][1], al[mt][2], al[mt][3], sb + SM_ALO + sa);
            }
            uint32_t bh[NT][2], bl[NT][2];
            #pragma unroll
            for (int np = 0; np < NT/2; np++) {
                int j = lane >> 3;
                int rn = wn*WN + np*16 + (lane & 7) + (j >> 1)*8;
                uint32_t sbo = swz((uint32_t)(rn*128 + ks*32 + (j & 1)*16));
                ldsm4(bh[2*np][0], bh[2*np][1], bh[2*np+1][0], bh[2*np+1][1], sb + SM_BHI + sbo);
                ldsm4(bl[2*np][0], bl[2*np][1], bl[2*np+1][0], bl[2*np+1][1], sb + SM_BLO + sbo);
            }
            #pragma unroll
            for (int mt = 0; mt < 2; mt++)
                #pragma unroll
                for (int nt = 0; nt < NT; nt++) {
                    mma16816(acc[mt][nt], ah[mt], bh[nt][0], bh[nt][1]);
                    mma16816(acc[mt][nt], al[mt], bh[nt][0], bh[nt][1]);
                    mma16816(acc[mt][nt], ah[mt], bl[nt][0], bl[nt][1]);
                }
        }
    }

    // ---- epilogue ----
    const float* bb = bias ? (MOE ? bias + (long)expert*sBiasE : bias) : nullptr;
    #pragma unroll
    for (int mt = 0; mt < 2; mt++) {
        int gm0 = row0 + wm*32 + mt*16 + (lane >> 2);
        #pragma unroll
        for (int half = 0; half < 2; half++) {
            int gm = gm0 + half*8;
            if (MOE && gm >= Meff) continue;
            long crow = MOE ? (long)(rbase + gm) : (long)gm;
            float* crp = Cb + crow*(long)ldc;
            const float* rrp = resb ? resb + crow*(long)ldc : nullptr;
            #pragma unroll
            for (int nt = 0; nt < NT; nt++) {
                int gn = col0 + wn*WN + nt*8 + 2*(lane & 3);
                #pragma unroll
                for (int q = 0; q < 2; q++) {
                    int gnn = gn + q;
                    if (gnn < N) {
                        float vv = acc[mt][nt][half*2 + q] * alpha;
                        if (bb)   vv += bb[gnn];
                        if (GELU) vv = gelu_f(vv);
                        if (rrp)  vv += rrp[gnn];
                        crp[gnn] = vv;
                    }
                }
            }
        }
    }
}

// ---------------- transpose z [B,C,S] -> zt [B*S, C] ----------------
__global__ void transpose_kernel(const float* __restrict__ z) {
    __shared__ float tile[32][33];
    int b  = blockIdx.z;
    int s0 = blockIdx.x*32, c0 = blockIdx.y*32;
    int tx = threadIdx.x, ty = threadIdx.y;
    tile[ty][tx] = z[((long)b*CIN + (c0+ty))*S_ + s0 + tx];
    __syncthreads();
    g_zt[((long)b*S_ + (s0+ty))*CIN + c0 + tx] = tile[tx][ty];
}

// ---------------- layernorm ----------------
__global__ void ln_kernel(const float* __restrict__ x, float* __restrict__ o,
                          const float* __restrict__ g, const float* __restrict__ b) {
    int row = blockIdx.x;
    const float* xr = x + (long)row*D_;
    __shared__ float red[256];
    int tid = threadIdx.x;
    float s = 0.f;
    for (int j = tid; j < D_; j += 256) s += xr[j];
    red[tid] = s; __syncthreads();
    for (int st = 128; st > 0; st >>= 1) { if (tid < st) red[tid] += red[tid+st]; __syncthreads(); }
    float mean = red[0] / D_;
    __syncthreads();
    float v = 0.f;
    for (int j = tid; j < D_; j += 256) { float d = xr[j]-mean; v += d*d; }
    red[tid] = v; __syncthreads();
    for (int st = 128; st > 0; st >>= 1) { if (tid < st) red[tid] += red[tid+st]; __syncthreads(); }
    float rstd = rsqrtf(red[0]/D_ + 1e-5f);
    for (int j = tid; j < D_; j += 256)
        o[(long)row*D_ + j] = (xr[j]-mean)*rstd*g[j] + b[j];
}

// ---------------- RoPE ----------------
__global__ void rope_kernel(float* q, float* k) {
    int t = blockIdx.x;
    int s = t % S_;
    int j = threadIdx.x;
    float inv = expf(-logf(10000.f) * ((float)j / 384.f));
    float ang = (float)s * inv;
    float sn, cs; sincosf(ang, &sn, &cs);
    long base = (long)t*D_ + 2*j;
    float x1 = q[base], x2 = q[base+1];
    q[base]   = x1*cs - x2*sn;
    q[base+1] = x1*sn + x2*cs;
    x1 = k[base]; x2 = k[base+1];
    k[base]   = x1*cs - x2*sn;
    k[base+1] = x1*sn + x2*cs;
}

// ---------------- causal softmax ----------------
__global__ void softmax_causal(float* __restrict__ sc) {
    long row = blockIdx.x;
    int i = (int)(row % S_);
    float* p = sc + row*(long)S_;
    int tid = threadIdx.x;
    __shared__ float red[256];
    float m = -1e30f;
    for (int j = tid; j <= i; j += 256) m = fmaxf(m, p[j]);
    red[tid] = m; __syncthreads();
    for (int st = 128; st > 0; st >>= 1) { if (tid < st) red[tid] = fmaxf(red[tid], red[tid+st]); __syncthreads(); }
    m = red[0]; __syncthreads();
    float s = 0.f;
    for (int j = tid; j <= i; j += 256) { float e = expf(p[j]-m); p[j] = e; s += e; }
    red[tid] = s; __syncthreads();
    for (int st = 128; st > 0; st >>= 1) { if (tid < st) red[tid] += red[tid+st]; __syncthreads(); }
    float inv = 1.f / red[0];
    for (int j = tid; j <= i; j += 256) p[j] *= inv;
    for (int j = i+1+tid; j < S_; j += 256) p[j] = 0.f;
}

// ---------------- MoE gating ----------------
__global__ void zero_cnt_kernel() { if (threadIdx.x < E_) g_cnt[threadIdx.x] = 0; }

__global__ void gate_kernel(const float* __restrict__ h, const float* __restrict__ gw) {
    int warp = threadIdx.x >> 5, lane = threadIdx.x & 31;
    int t = blockIdx.x*8 + warp;
    if (t >= NTOK) return;
    const float* hr = h + (long)t*D_;
    float lg[E_];
    #pragma unroll
    for (int e = 0; e < E_; e++) lg[e] = 0.f;
    for (int d = lane; d < D_; d += 32) {
        float hv = hr[d];
        #pragma unroll
        for (int e = 0; e < E_; e++) lg[e] += hv * gw[(long)d*E_ + e];
    }
    #pragma unroll
    for (int e = 0; e < E_; e++)
        for (int st = 16; st > 0; st >>= 1) lg[e] += __shfl_xor_sync(0xffffffffu, lg[e], st);
    if (lane == 0) {
        int i0 = 0; float v0 = lg[0];
        for (int e = 1; e < E_; e++) if (lg[e] > v0) { v0 = lg[e]; i0 = e; }
        int i1 = -1; float v1 = -1e30f;
        for (int e = 0; e < E_; e++) if (e != i0 && lg[e] > v1) { v1 = lg[e]; i1 = e; }
        float e1 = expf(v1 - v0);
        float inv = 1.f/(1.f+e1);
        g_topi[t*2] = i0;   g_topi[t*2+1] = i1;
        g_topw[t*2] = inv;  g_topw[t*2+1] = e1*inv;
        g_rank[t*2]   = atomicAdd(&g_cnt[i0], 1);
        g_rank[t*2+1] = atomicAdd(&g_cnt[i1], 1);
    }
}

__global__ void scan_kernel() {
    g_off[0] = 0;
    int nb = 0;
    for (int e = 0; e < E_; e++) {
        g_off[e+1] = g_off[e] + g_cnt[e];
        int tiles = (g_cnt[e] + 127) / 128;
        for (int tI = 0; tI < tiles; tI++) g_blkmap[nb++] = (e << 16) | tI;
    }
    g_nblk[0] = nb;
}

__global__ void fill_slots_kernel() {
    int idx = blockIdx.x*256 + threadIdx.x;
    if (idx >= NSLOT) return;
    int e = g_topi[idx];
    int slot = g_off[e] + g_rank[idx];
    g_slot_tok[slot] = idx >> 1;
    g_tok_slot[idx] = slot;
}

__global__ void combine_kernel(float* __restrict__ x) {
    int t = blockIdx.x;
    int s0 = g_tok_slot[t*2], s1 = g_tok_slot[t*2+1];
    float w0 = g_topw[t*2], w1 = g_topw[t*2+1];
    for (int j = threadIdx.x; j < D_; j += 256)
        x[(long)t*D_+j] += w0*g_y[(long)s0*D_+j] + w1*g_y[(long)s1*D_+j];
}

// ---------------- windowed inverse-DFT matrix ----------------
__global__ void dft_build_kernel() {
    int r = blockIdx.y;
    int n = blockIdx.x*256 + threadIdx.x;
    const float TWO_PI = 6.283185307179586477f;
    float win = 0.5f*(1.f - cosf(TWO_PI * (float)n / (float)NFFT_));
    float val;
    if (r < FB_) {
        float w = (r == 0 || r == FB_-1) ? 1.f : 2.f;
        int ph = (r*n) & (NFFT_-1);
        val = (w/(float)NFFT_) * cosf(TWO_PI * (float)ph / (float)NFFT_) * win;
    } else {
        int r2 = r - FB_;
        float w = (r2 == 0 || r2 == FB_-1) ? 1.f : 2.f;
        int ph = (r2*n) & (NFFT_-1);
        val = -(w/(float)NFFT_) * sinf(TWO_PI * (float)ph / (float)NFFT_) * win;
    }
    g_dft[(long)r*NFFT_ + n] = val;
}

// ---------------- overlap-add ----------------
__global__ void ola_kernel(float* __restrict__ out) {
    int b = blockIdx.y;
    int p = blockIdx.x*256 + threadIdx.x;
    int g = p + PAD_;
    int tmin = (g >= WIN_-1) ? ((g - (WIN_-1) + HOP_-1) >> 8) : 0;
    int tmax = g >> 8;
    if (tmax > S_-1) tmax = S_-1;
    const float TWO_PI = 6.283185307179586477f;
    float acc = 0.f, env = 0.f;
    for (int t = tmin; t <= tmax; t++) {
        int n = g - t*HOP_;
        float win = 0.5f*(1.f - cosf(TWO_PI * (float)n / (float)WIN_));
        acc += g_frames[((long)(b*S_ + t))*NFFT_ + n];
        env += win*win;
    }
    out[(long)b*OUTL + p] = acc/env;
}

// ---------------- host orchestration ----------------
#define SMEM128 65536   // A hi/lo 32KB + B hi/lo 32KB
#define SMEM64  49152   // A hi/lo 32KB + B hi/lo 16KB

extern "C" void kernel_launch(void* const* d_in, const int* in_sizes, int n_in,
                              void* d_out, int out_size) {
    (void)in_sizes; (void)n_in; (void)out_size;
    const float* z     = (const float*)d_in[0];
    const float* in_w  = (const float*)d_in[1];
    const float* in_b  = (const float*)d_in[2];
    const float* ln1_g = (const float*)d_in[3];
    const float* ln1_b = (const float*)d_in[4];
    const float* wq    = (const float*)d_in[5];
    const float* bq    = (const float*)d_in[6];
    const float* wk    = (const float*)d_in[7];
    const float* bk    = (const float*)d_in[8];
    const float* wv    = (const float*)d_in[9];
    const float* bv    = (const float*)d_in[10];
    const float* wo    = (const float*)d_in[11];
    const float* bo    = (const float*)d_in[12];
    const float* ln2_g = (const float*)d_in[13];
    const float* ln2_b = (const float*)d_in[14];
    const float* gatew = (const float*)d_in[15];
    const float* e_w1  = (const float*)d_in[16];
    const float* e_b1  = (const float*)d_in[17];
    const float* e_w2  = (const float*)d_in[18];
    const float* e_b2  = (const float*)d_in[19];
    const float* out_w = (const float*)d_in[20];
    const float* out_b = (const float*)d_in[21];
    float* out = (float*)d_out;

    float *p_zt,*p_x,*p_h,*p_q,*p_k,*p_v,*p_ctx,*p_sc,*p_h1,*p_y,*p_s,*p_fr,*p_dft;
    int *p_slot_tok,*p_off,*p_blkmap,*p_nblk;
    cudaGetSymbolAddress((void**)&p_zt, g_zt);
    cudaGetSymbolAddress((void**)&p_x,  g_x);
    cudaGetSymbolAddress((void**)&p_h,  g_h);
    cudaGetSymbolAddress((void**)&p_q,  g_q);
    cudaGetSymbolAddress((void**)&p_k,  g_k);
    cudaGetSymbolAddress((void**)&p_v,  g_v);
    cudaGetSymbolAddress((void**)&p_ctx,g_ctx);
    cudaGetSymbolAddress((void**)&p_sc, g_sc);
    cudaGetSymbolAddress((void**)&p_h1, g_h1);
    cudaGetSymbolAddress((void**)&p_y,  g_y);
    cudaGetSymbolAddress((void**)&p_s,  g_sout);
    cudaGetSymbolAddress((void**)&p_fr, g_frames);
    cudaGetSymbolAddress((void**)&p_dft,g_dft);
    cudaGetSymbolAddress((void**)&p_slot_tok, g_slot_tok);
    cudaGetSymbolAddress((void**)&p_off,    g_off);
    cudaGetSymbolAddress((void**)&p_blkmap, g_blkmap);
    cudaGetSymbolAddress((void**)&p_nblk,   g_nblk);

    cudaFuncSetAttribute((const void*)gemmtc<false,false,false,128,false,false>,
                         cudaFuncAttributeMaxDynamicSharedMemorySize, SMEM128);
    cudaFuncSetAttribute((const void*)gemmtc<true,false,false,128,true,false>,
                         cudaFuncAttributeMaxDynamicSharedMemorySize, SMEM128);
    cudaFuncSetAttribute((const void*)gemmtc<false,false,false,64,false,true>,
                         cudaFuncAttributeMaxDynamicSharedMemorySize, SMEM64);
    cudaFuncSetAttribute((const void*)gemmtc<false,true,true,128,false,false>,
                         cudaFuncAttributeMaxDynamicSharedMemorySize, SMEM128);
    cudaFuncSetAttribute((const void*)gemmtc<false,false,true,128,false,false>,
                         cudaFuncAttributeMaxDynamicSharedMemorySize, SMEM128);

    // in-projection
    transpose_kernel<<<dim3(S_/32, CIN/32, B_), dim3(32,32)>>>(z);
    gemmtc<false,false,false,128,false,false><<<dim3(6,16,1), 256, SMEM128>>>(
        p_zt, CIN, 0,0, in_w, D_, 0,0, p_x, D_, 0,0,
        in_b, 0, nullptr, NTOK, D_, CIN, 1.f, 1,
        nullptr, nullptr, nullptr, nullptr, 0);

    for (int i = 0; i < L_; i++) {
        // ---- attention ----
        ln_kernel<<<NTOK,256>>>(p_x, p_h, ln1_g + i*D_, ln1_b + i*D_);
        gemmtc<false,false,false,128,false,false><<<dim3(6,16,1), 256, SMEM128>>>(
            p_h, D_, 0,0, wq + (long)i*D_*D_, D_, 0,0, p_q, D_, 0,0,
            bq + i*D_, 0, nullptr, NTOK, D_, D_, 1.f, 1, nullptr,nullptr,nullptr,nullptr,0);
        gemmtc<false,false,false,128,false,false><<<dim3(6,16,1), 256, SMEM128>>>(
            p_h, D_, 0,0, wk + (long)i*D_*D_, D_, 0,0, p_k, D_, 0,0,
            bk + i*D_, 0, nullptr, NTOK, D_, D_, 1.f, 1, nullptr,nullptr,nullptr,nullptr,0);
        gemmtc<false,false,false,128,false,false><<<dim3(6,16,1), 256, SMEM128>>>(
            p_h, D_, 0,0, wv + (long)i*D_*D_, D_, 0,0, p_v, D_, 0,0,
            bv + i*D_, 0, nullptr, NTOK, D_, D_, 1.f, 1, nullptr,nullptr,nullptr,nullptr,0);
        if (i == 0) rope_kernel<<<NTOK,384>>>(p_q, p_k);

        // scores = (Q @ K^T) * 1/sqrt(HD), fully-masked tiles skipped
        gemmtc<true,false,false,128,true,false><<<dim3(8,8,B_*H_), 256, SMEM128>>>(
            p_q, D_, (long)S_*D_, 64, p_k, D_, (long)S_*D_, 64,
            p_sc, S_, (long)H_*S_*S_, (long)S_*S_,
            nullptr, 0, nullptr, S_, S_, HD_, 0.125f, H_,
            nullptr,nullptr,nullptr,nullptr,0);
        softmax_causal<<<B_*H_*S_,256>>>(p_sc);
        // ctx = att @ V (K limited to causal extent)
        gemmtc<false,false,false,64,false,true><<<dim3(1,8,B_*H_), 256, SMEM64>>>(
            p_sc, S_, (long)H_*S_*S_, (long)S_*S_, p_v, D_, (long)S_*D_, 64,
            p_ctx, D_, (long)S_*D_, 64,
            nullptr, 0, nullptr, S_, HD_, S_, 1.f, H_,
            nullptr,nullptr,nullptr,nullptr,0);
        // x += ctx @ Wo + bo
        gemmtc<false,false,false,128,false,false><<<dim3(6,16,1), 256, SMEM128>>>(
            p_ctx, D_, 0,0, wo + (long)i*D_*D_, D_, 0,0, p_x, D_, 0,0,
            bo + i*D_, 0, p_x, NTOK, D_, D_, 1.f, 1, nullptr,nullptr,nullptr,nullptr,0);

        // ---- MoE ----
        ln_kernel<<<NTOK,256>>>(p_x, p_h, ln2_g + i*D_, ln2_b + i*D_);
        zero_cnt_kernel<<<1,32>>>();
        gate_kernel<<<NTOK/8,256>>>(p_h, gatew + (long)i*D_*E_);
        scan_kernel<<<1,1>>>();
        fill_slots_kernel<<<(NSLOT+255)/256,256>>>();
        gemmtc<false,true,true,128,false,false><<<dim3(16,40,1), 256, SMEM128>>>(
            p_h, D_, 0,0, e_w1 + (long)i*E_*D_*FF_, FF_, 0,0,
            p_h1, FF_, 0,0, e_b1 + (long)i*E_*FF_, FF_,
            nullptr, 0, FF_, D_, 1.f, 1,
            p_slot_tok, p_off, p_blkmap, p_nblk, (long)D_*FF_);
        gemmtc<false,false,true,128,false,false><<<dim3(6,40,1), 256, SMEM128>>>(
            p_h1, FF_, 0,0, e_w2 + (long)i*E_*FF_*D_, D_, 0,0,
            p_y, D_, 0,0, e_b2 + (long)i*E_*D_, D_,
            nullptr, 0, D_, FF_, 1.f, 1,
            nullptr, p_off, p_blkmap, p_nblk, (long)FF_*D_);
        combine_kernel<<<NTOK,256>>>(p_x);
    }

    // spectral head: s = x @ out_w + out_b  [2048, 1026] (ldc padded to 1028)
    gemmtc<false,false,false,128,false,false><<<dim3(9,16,1), 256, SMEM128>>>(
        p_x, D_, 0,0, out_w, 2*FB_, 0,0, p_s, SLD, 0,0,
        out_b, 0, nullptr, NTOK, 2*FB_, D_, 1.f, 1,
        nullptr,nullptr,nullptr,nullptr,0);

    // windowed inverse DFT as GEMM: frames = s @ M  [2048, 1024]
    dft_build_kernel<<<dim3(NFFT_/256, 2*FB_), 256>>>();
    gemmtc<false,false,false,128,false,false><<<dim3(8,16,1), 256, SMEM128>>>(
        p_s, SLD, 0,0, p_dft, NFFT_, 0,0, p_fr, NFFT_, 0,0,
        nullptr, 0, nullptr, NTOK, NFFT_, 2*FB_, 1.f, 1,
        nullptr,nullptr,nullptr,nullptr,0);

    ola_kernel<<<dim3(OUTL/256, B_), 256>>>(out);
}